// round 2
// baseline (speedup 1.0000x reference)
#include <cuda_runtime.h>
#include <math.h>

// Problem constants
#define Bn   64
#define Sn   256
#define Dn   300
#define NWn  8192
#define CLn  16
#define CDn  30
#define CHn  30
#define Hn   128
#define Tn   17
#define INW0 330   // D + CH
#define G3   384   // 3*H
#define G6   768   // 2 dirs * 3H

// ---------------- device scratch (static, no allocation) ----------------
__device__ float g_tokenc[(NWn + 1) * CHn];
__device__ float g_texts[(size_t)Bn * Sn * INW0];
__device__ float g_xg[(size_t)Bn * Sn * G6];
__device__ float g_h0[(size_t)Bn * Sn * 256];
__device__ float g_h1[(size_t)Bn * Sn * 256];
__device__ float g_mlp[(size_t)Bn * Sn * Hn];
__device__ float g_emis[(size_t)Bn * Sn * Tn + 64];
__device__ float g_llh[Bn];

// ---------------- char CNN ----------------
__global__ void char_cnn_kernel(const float* __restrict__ char_emb,
                                const float* __restrict__ conv_w,
                                const float* __restrict__ conv_b,
                                const int* __restrict__ words) {
    __shared__ float s_emb[CLn + 2][CDn];
    __shared__ float s_w[CHn * CDn * 3];
    __shared__ float s_out[CHn * CLn];
    __shared__ int   s_idx[CLn];
    int tid = threadIdx.x;
    int blk = blockIdx.x;
    if (blk == 0) {
        if (tid < CHn) g_tokenc[tid] = 0.f;
        return;
    }
    int w = blk - 1;
    if (tid < CLn) s_idx[tid] = words[w * CLn + tid];
    for (int i = tid; i < CHn * CDn * 3; i += blockDim.x) s_w[i] = conv_w[i];
    if (tid < CDn) { s_emb[0][tid] = 0.f; s_emb[CLn + 1][tid] = 0.f; }
    __syncthreads();
    if (tid < CLn * CDn) {
        int t = tid / CDn, d = tid % CDn;
        s_emb[t + 1][d] = char_emb[s_idx[t] * CDn + d];
    }
    __syncthreads();
    {
        int ch = tid / CLn, t = tid % CLn;
        float acc = conv_b[ch];
        const float* wr = &s_w[ch * CDn * 3];
#pragma unroll
        for (int d = 0; d < CDn; ++d) {
            acc += s_emb[t][d]     * wr[d * 3 + 0];
            acc += s_emb[t + 1][d] * wr[d * 3 + 1];
            acc += s_emb[t + 2][d] * wr[d * 3 + 2];
        }
        s_out[ch * CLn + t] = fmaxf(acc, 0.f);
    }
    __syncthreads();
    if (tid < CHn) {
        float m = s_out[tid * CLn];
#pragma unroll
        for (int t = 1; t < CLn; ++t) m = fmaxf(m, s_out[tid * CLn + t]);
        g_tokenc[(w + 1) * CHn + tid] = m;
    }
}

// ---------------- build texts ----------------
__global__ void build_texts_kernel(const float* __restrict__ word_emb,
                                   const int* __restrict__ tokens,
                                   const int* __restrict__ cwi) {
    int m = blockIdx.x;
    int tid = threadIdx.x;
    int tok = tokens[m];
    int ci = cwi[m];
    if (tid < Dn)
        g_texts[(size_t)m * INW0 + tid] = word_emb[(size_t)tok * Dn + tid];
    else if (tid < INW0)
        g_texts[(size_t)m * INW0 + tid] = g_tokenc[ci * CHn + (tid - Dn)];
}

// ---------------- SGEMM 128x64 tile, 8x4 per thread ----------------
// C[M][N] = A[M][K] * W(+bias); wNK=1: W is [N][K]; wNK=0: W is [K][N].
__global__ void gemm_kernel(const float* __restrict__ A,
                            const float* __restrict__ W,
                            const float* __restrict__ bias,
                            float* __restrict__ C,
                            int M, int N, int K, int relu, int wNK) {
    __shared__ float As[16][129];
    __shared__ float Ws[16][65];
    int tid = threadIdx.x;
    int tx = tid % 16, ty = tid / 16;
    int m0 = blockIdx.y * 128, n0 = blockIdx.x * 64;
    float acc[8][4] = {};
    int ktiles = (K + 15) / 16;
    for (int kt = 0; kt < ktiles; ++kt) {
        int k0 = kt * 16;
#pragma unroll
        for (int l = 0; l < 8; ++l) {             // A tile: 128x16
            int e = tid + l * 256;
            int kk = e % 16, i = e / 16;
            int m = m0 + i, k = k0 + kk;
            As[kk][i] = (k < K && m < M) ? A[(size_t)m * K + k] : 0.f;
        }
#pragma unroll
        for (int l = 0; l < 4; ++l) {             // W tile: 64x16
            int e = tid + l * 256;
            int kk = e % 16, i = e / 16;
            int n = n0 + i, k = k0 + kk;
            float wv = 0.f;
            if (k < K && n < N)
                wv = wNK ? W[(size_t)n * K + k] : W[(size_t)k * N + n];
            Ws[kk][i] = wv;
        }
        __syncthreads();
#pragma unroll
        for (int kk = 0; kk < 16; ++kk) {
            float a[8], b[4];
#pragma unroll
            for (int i = 0; i < 8; ++i) a[i] = As[kk][ty * 8 + i];
#pragma unroll
            for (int j = 0; j < 4; ++j) b[j] = Ws[kk][tx * 4 + j];
#pragma unroll
            for (int i = 0; i < 8; ++i)
#pragma unroll
                for (int j = 0; j < 4; ++j)
                    acc[i][j] += a[i] * b[j];
        }
        __syncthreads();
    }
#pragma unroll
    for (int i = 0; i < 8; ++i) {
        int m = m0 + ty * 8 + i;
        if (m >= M) continue;
#pragma unroll
        for (int j = 0; j < 4; ++j) {
            int n = n0 + tx * 4 + j;
            if (n >= N) continue;
            float v = acc[i][j] + bias[n];
            if (relu) v = fmaxf(v, 0.f);
            C[(size_t)m * N + n] = v;
        }
    }
}

// ---------------- GRU scan: 2 batches per block, shared W_hh ----------------
// grid = 64 blocks: dir = blk/32, batches 2*(blk%32), +1. 768 threads.
#define GRU_SMEM (384 * 132 * 4 + 2 * 128 * 4 + 2 * 384 * 4)

__global__ void gru_kernel(const float* __restrict__ xg,    // [B*S][768]
                           const float* __restrict__ w_hh,  // [2][384][128]
                           const float* __restrict__ b_hh,  // [2][384]
                           const int* __restrict__ lens,
                           float* __restrict__ out) {       // [B*S][256]
    extern __shared__ float sm[];
    float* Wp = sm;                        // [384][132]
    float* sh_hA  = sm + 384 * 132;        // [2][128]
    float* sh_hgA = sh_hA + 2 * 128;       // [2][384]
    int tid = threadIdx.x;
    int sub = tid / G3;                    // 0 or 1 (warp-aligned: 384=12 warps)
    int g   = tid % G3;
    int dir = blockIdx.x >> 5;
    int b   = ((blockIdx.x & 31) << 1) + sub;

    const float* Wg = w_hh + (size_t)dir * G3 * Hn;
    for (int i = tid; i < G3 * Hn; i += 2 * G3) {
        int gg = i >> 7, k = i & 127;
        Wp[gg * 132 + k] = Wg[i];
    }
    float* sh_h  = sh_hA + sub * 128;
    float* sh_hg = sh_hgA + sub * G3;
    if (g < Hn) sh_h[g] = 0.f;
    float bh = b_hh[dir * G3 + g];
    int len = lens[b];
    const float* xgb = xg + (size_t)b * Sn * G6 + dir * G3;
    float* outb = out + (size_t)b * Sn * 256 + dir * Hn;
    __syncthreads();

    const float4* Wp4 = (const float4*)(Wp + g * 132);
    const float4* h4 = (const float4*)sh_h;
    for (int t = 0; t < Sn; ++t) {
        int s = dir ? (Sn - 1 - t) : t;
        float acc0 = 0.f, acc1 = 0.f, acc2 = 0.f, acc3 = 0.f;
#pragma unroll
        for (int k4 = 0; k4 < 32; k4 += 4) {
            float4 w0 = Wp4[k4 + 0], hh0 = h4[k4 + 0];
            float4 w1 = Wp4[k4 + 1], hh1 = h4[k4 + 1];
            float4 w2 = Wp4[k4 + 2], hh2 = h4[k4 + 2];
            float4 w3 = Wp4[k4 + 3], hh3 = h4[k4 + 3];
            acc0 += w0.x * hh0.x + w0.y * hh0.y + w0.z * hh0.z + w0.w * hh0.w;
            acc1 += w1.x * hh1.x + w1.y * hh1.y + w1.z * hh1.z + w1.w * hh1.w;
            acc2 += w2.x * hh2.x + w2.y * hh2.y + w2.z * hh2.z + w2.w * hh2.w;
            acc3 += w3.x * hh3.x + w3.y * hh3.y + w3.z * hh3.z + w3.w * hh3.w;
        }
        sh_hg[g] = bh + ((acc0 + acc1) + (acc2 + acc3));
        __syncthreads();
        if (g < Hn) {
            const float* xs = xgb + (size_t)s * G6;
            float xr = xs[g], xz = xs[Hn + g], xn = xs[2 * Hn + g];
            float hr = sh_hg[g], hz = sh_hg[Hn + g], hn = sh_hg[2 * Hn + g];
            float r = 1.f / (1.f + expf(-(xr + hr)));
            float z = 1.f / (1.f + expf(-(xz + hz)));
            float n = tanhf(xn + r * hn);
            float hp = sh_h[g];
            float hv = (s < len) ? ((1.f - z) * n + z * hp) : hp;
            sh_h[g] = hv;
            outb[(size_t)s * 256 + g] = hv;
        }
        __syncthreads();
    }
}

// ---------------- CRF ----------------
__global__ void crf_kernel(const float* __restrict__ start,
                           const float* __restrict__ end_,
                           const float* __restrict__ trans,
                           const int* __restrict__ target,
                           const int* __restrict__ lens) {
    int b = blockIdx.x, lane = threadIdx.x;
    const float* E = g_emis + (size_t)b * Sn * Tn;
    const int* tgt = target + b * Sn;
    int len = lens[b];

    float partial = 0.f;
    for (int s = 1 + lane; s < Sn; s += 32) {
        if (s < len)
            partial += trans[tgt[s - 1] * Tn + tgt[s]] + E[s * Tn + tgt[s]];
    }
#pragma unroll
    for (int o = 16; o; o >>= 1) partial += __shfl_down_sync(0xffffffffu, partial, o);

    float tc[Tn];
    float alpha = -1e30f;
    if (lane < Tn) {
        alpha = start[lane] + E[lane];
#pragma unroll
        for (int i = 0; i < Tn; ++i) tc[i] = trans[i * Tn + lane];
    } else {
#pragma unroll
        for (int i = 0; i < Tn; ++i) tc[i] = 0.f;
    }
    for (int s = 1; s < Sn; ++s) {
        float av[Tn];
        float mx = -1e30f;
#pragma unroll
        for (int i = 0; i < Tn; ++i) {
            av[i] = __shfl_sync(0xffffffffu, alpha, i) + tc[i];
            mx = fmaxf(mx, av[i]);
        }
        float sum = 0.f;
#pragma unroll
        for (int i = 0; i < Tn; ++i) sum += expf(av[i] - mx);
        float e = (lane < Tn) ? E[s * Tn + lane] : 0.f;
        float nw = mx + logf(sum) + e;
        if (lane < Tn && s < len) alpha = nw;
    }
    float v = (lane < Tn) ? alpha + end_[lane] : -1e30f;
    float mx = v;
#pragma unroll
    for (int o = 16; o; o >>= 1) mx = fmaxf(mx, __shfl_xor_sync(0xffffffffu, mx, o));
    float se = expf(v - mx);
#pragma unroll
    for (int o = 16; o; o >>= 1) se += __shfl_xor_sync(0xffffffffu, se, o);
    float logz = mx + logf(se);
    if (lane == 0) {
        float score = partial + start[tgt[0]] + E[tgt[0]] + end_[tgt[len - 1]];
        g_llh[b] = score - logz;
    }
}

__global__ void finalize_kernel(const int* __restrict__ lens, float* __restrict__ out) {
    float sl = 0.f;
    float smk = 0.f;
    for (int b = 0; b < Bn; ++b) { sl += g_llh[b]; smk += (float)lens[b]; }
    out[0] = -sl / smk;
}

// ---------------- launch ----------------
extern "C" void kernel_launch(void* const* d_in, const int* in_sizes, int n_in,
                              void* d_out, int out_size) {
    const float* char_emb  = (const float*)d_in[0];
    const float* conv_w    = (const float*)d_in[1];
    const float* conv_b    = (const float*)d_in[2];
    const float* word_emb  = (const float*)d_in[3];
    const float* w_ih_l0   = (const float*)d_in[4];
    const float* w_hh_l0   = (const float*)d_in[5];
    const float* b_ih_l0   = (const float*)d_in[6];
    const float* b_hh_l0   = (const float*)d_in[7];
    const float* w_ih_l1   = (const float*)d_in[8];
    const float* w_hh_l1   = (const float*)d_in[9];
    const float* b_ih_l1   = (const float*)d_in[10];
    const float* b_hh_l1   = (const float*)d_in[11];
    const float* mlp_w1    = (const float*)d_in[12];
    const float* mlp_b1    = (const float*)d_in[13];
    const float* mlp_w2    = (const float*)d_in[14];
    const float* mlp_b2    = (const float*)d_in[15];
    const float* crf_start = (const float*)d_in[16];
    const float* crf_end   = (const float*)d_in[17];
    const float* crf_trans = (const float*)d_in[18];
    const int* char_words  = (const int*)d_in[19];
    const int* cwi         = (const int*)d_in[21];
    const int* tokens      = (const int*)d_in[22];
    const int* tokens_len  = (const int*)d_in[23];
    const int* target      = (const int*)d_in[24];
    float* out = (float*)d_out;

    void* pv;
    cudaGetSymbolAddress(&pv, g_texts); float* p_texts = (float*)pv;
    cudaGetSymbolAddress(&pv, g_xg);    float* p_xg    = (float*)pv;
    cudaGetSymbolAddress(&pv, g_h0);    float* p_h0    = (float*)pv;
    cudaGetSymbolAddress(&pv, g_h1);    float* p_h1    = (float*)pv;
    cudaGetSymbolAddress(&pv, g_mlp);   float* p_mlp   = (float*)pv;
    cudaGetSymbolAddress(&pv, g_emis);  float* p_emis  = (float*)pv;

    cudaFuncSetAttribute(gru_kernel, cudaFuncAttributeMaxDynamicSharedMemorySize, GRU_SMEM);

    const int M = Bn * Sn;  // 16384

    char_cnn_kernel<<<NWn + 1, 480>>>(char_emb, conv_w, conv_b, char_words);
    build_texts_kernel<<<M, 352>>>(word_emb, tokens, cwi);
    gemm_kernel<<<dim3(G6 / 64, M / 128), 256>>>(p_texts, w_ih_l0, b_ih_l0, p_xg,
                                                 M, G6, INW0, 0, 1);
    gru_kernel<<<64, 2 * G3, GRU_SMEM>>>(p_xg, w_hh_l0, b_hh_l0, tokens_len, p_h0);
    gemm_kernel<<<dim3(G6 / 64, M / 128), 256>>>(p_h0, w_ih_l1, b_ih_l1, p_xg,
                                                 M, G6, 256, 0, 1);
    gru_kernel<<<64, 2 * G3, GRU_SMEM>>>(p_xg, w_hh_l1, b_hh_l1, tokens_len, p_h1);
    gemm_kernel<<<dim3(Hn / 64, M / 128), 256>>>(p_h1, mlp_w1, mlp_b1, p_mlp,
                                                 M, Hn, 256, 1, 0);
    gemm_kernel<<<dim3(1, M / 128), 256>>>(p_mlp, mlp_w2, mlp_b2, p_emis,
                                           M, Tn, Hn, 0, 0);
    crf_kernel<<<Bn, 32>>>(crf_start, crf_end, crf_trans, target, tokens_len);
    finalize_kernel<<<1, 1>>>(tokens_len, out);
}

// round 3
// speedup vs baseline: 1.4002x; 1.4002x over previous
#include <cuda_runtime.h>
#include <math.h>

// Problem constants
#define Bn   64
#define Sn   256
#define Dn   300
#define NWn  8192
#define CLn  16
#define CDn  30
#define CHn  30
#define Hn   128
#define Tn   17
#define INW0 330   // D + CH
#define G3   384   // 3*H
#define G6   768   // 2 dirs * 3H

typedef unsigned long long ull;

// ---------------- f32x2 helpers (FFMA2) ----------------
__device__ __forceinline__ ull pk2(float lo, float hi) {
    ull r; asm("mov.b64 %0,{%1,%2};" : "=l"(r) : "f"(lo), "f"(hi)); return r;
}
__device__ __forceinline__ void ffma2(ull& acc, ull a, ull b) {
    asm("fma.rn.f32x2 %0,%1,%2,%0;" : "+l"(acc) : "l"(a), "l"(b));
}
__device__ __forceinline__ void upk2(ull v, float& lo, float& hi) {
    asm("mov.b64 {%0,%1},%2;" : "=f"(lo), "=f"(hi) : "l"(v));
}

// ---------------- device scratch (static, no allocation) ----------------
__device__ float g_tokenc[(NWn + 1) * CHn];
__device__ float g_texts[(size_t)Bn * Sn * INW0];
__device__ float g_xg[(size_t)Bn * Sn * G6];
__device__ float g_h0[(size_t)Bn * Sn * 256];
__device__ float g_h1[(size_t)Bn * Sn * 256];
__device__ float g_mlp[(size_t)Bn * Sn * Hn];
__device__ float g_emis[(size_t)Bn * Sn * Tn + 64];
__device__ float g_llh[Bn];

// ---------------- char CNN ----------------
__global__ void char_cnn_kernel(const float* __restrict__ char_emb,
                                const float* __restrict__ conv_w,
                                const float* __restrict__ conv_b,
                                const int* __restrict__ words) {
    __shared__ float s_emb[CLn + 2][CDn];
    __shared__ float s_w[CHn * CDn * 3];
    __shared__ float s_out[CHn * CLn];
    __shared__ int   s_idx[CLn];
    int tid = threadIdx.x;
    int blk = blockIdx.x;
    if (blk == 0) {
        if (tid < CHn) g_tokenc[tid] = 0.f;
        return;
    }
    int w = blk - 1;
    if (tid < CLn) s_idx[tid] = words[w * CLn + tid];
    for (int i = tid; i < CHn * CDn * 3; i += blockDim.x) s_w[i] = conv_w[i];
    if (tid < CDn) { s_emb[0][tid] = 0.f; s_emb[CLn + 1][tid] = 0.f; }
    __syncthreads();
    if (tid < CLn * CDn) {
        int t = tid / CDn, d = tid % CDn;
        s_emb[t + 1][d] = char_emb[s_idx[t] * CDn + d];
    }
    __syncthreads();
    {
        int ch = tid / CLn, t = tid % CLn;
        float acc = conv_b[ch];
        const float* wr = &s_w[ch * CDn * 3];
#pragma unroll
        for (int d = 0; d < CDn; ++d) {
            acc += s_emb[t][d]     * wr[d * 3 + 0];
            acc += s_emb[t + 1][d] * wr[d * 3 + 1];
            acc += s_emb[t + 2][d] * wr[d * 3 + 2];
        }
        s_out[ch * CLn + t] = fmaxf(acc, 0.f);
    }
    __syncthreads();
    if (tid < CHn) {
        float m = s_out[tid * CLn];
#pragma unroll
        for (int t = 1; t < CLn; ++t) m = fmaxf(m, s_out[tid * CLn + t]);
        g_tokenc[(w + 1) * CHn + tid] = m;
    }
}

// ---------------- build texts ----------------
__global__ void build_texts_kernel(const float* __restrict__ word_emb,
                                   const int* __restrict__ tokens,
                                   const int* __restrict__ cwi) {
    int m = blockIdx.x;
    int tid = threadIdx.x;
    int tok = tokens[m];
    int ci = cwi[m];
    if (tid < Dn)
        g_texts[(size_t)m * INW0 + tid] = word_emb[(size_t)tok * Dn + tid];
    else if (tid < INW0)
        g_texts[(size_t)m * INW0 + tid] = g_tokenc[ci * CHn + (tid - Dn)];
}

// ---------------- SGEMM 128x64 tile, 8x4 per thread, FFMA2 inner ----------------
// C[M][N] = A[M][K] * W(+bias); wNK=1: W is [N][K]; wNK=0: W is [K][N].
__global__ void gemm_kernel(const float* __restrict__ A,
                            const float* __restrict__ W,
                            const float* __restrict__ bias,
                            float* __restrict__ C,
                            int M, int N, int K, int relu, int wNK) {
    __shared__ float As[16][132];   // pitch 132 floats = 528B (16B aligned rows)
    __shared__ float Ws[16][68];    // pitch 68 floats  = 272B (16B aligned rows)
    int tid = threadIdx.x;
    int tx = tid % 16, ty = tid / 16;
    int m0 = blockIdx.y * 128, n0 = blockIdx.x * 64;
    ull acc2[4][4];                 // [i-pair][j], each lane pair = rows (2ip, 2ip+1)
#pragma unroll
    for (int ip = 0; ip < 4; ++ip)
#pragma unroll
        for (int j = 0; j < 4; ++j) acc2[ip][j] = pk2(0.f, 0.f);

    int ktiles = (K + 15) / 16;
    for (int kt = 0; kt < ktiles; ++kt) {
        int k0 = kt * 16;
#pragma unroll
        for (int l = 0; l < 8; ++l) {             // A tile: 128x16
            int e = tid + l * 256;
            int kk = e % 16, i = e / 16;
            int m = m0 + i, k = k0 + kk;
            As[kk][i] = (k < K && m < M) ? A[(size_t)m * K + k] : 0.f;
        }
#pragma unroll
        for (int l = 0; l < 4; ++l) {             // W tile: 64x16
            int e = tid + l * 256;
            int kk = e % 16, i = e / 16;
            int n = n0 + i, k = k0 + kk;
            float wv = 0.f;
            if (k < K && n < N)
                wv = wNK ? W[(size_t)n * K + k] : W[(size_t)k * N + n];
            Ws[kk][i] = wv;
        }
        __syncthreads();
#pragma unroll
        for (int kk = 0; kk < 16; ++kk) {
            float4 a0 = *(const float4*)&As[kk][ty * 8];
            float4 a1 = *(const float4*)&As[kk][ty * 8 + 4];
            float4 b4 = *(const float4*)&Ws[kk][tx * 4];
            ull ap[4];
            ap[0] = pk2(a0.x, a0.y); ap[1] = pk2(a0.z, a0.w);
            ap[2] = pk2(a1.x, a1.y); ap[3] = pk2(a1.z, a1.w);
            ull bb0 = pk2(b4.x, b4.x), bb1 = pk2(b4.y, b4.y);
            ull bb2 = pk2(b4.z, b4.z), bb3 = pk2(b4.w, b4.w);
#pragma unroll
            for (int ip = 0; ip < 4; ++ip) {
                ffma2(acc2[ip][0], ap[ip], bb0);
                ffma2(acc2[ip][1], ap[ip], bb1);
                ffma2(acc2[ip][2], ap[ip], bb2);
                ffma2(acc2[ip][3], ap[ip], bb3);
            }
        }
        __syncthreads();
    }
#pragma unroll
    for (int ip = 0; ip < 4; ++ip) {
#pragma unroll
        for (int j = 0; j < 4; ++j) {
            float v0, v1;
            upk2(acc2[ip][j], v0, v1);
            int n = n0 + tx * 4 + j;
            if (n >= N) continue;
            float bsv = bias[n];
            int mA = m0 + ty * 8 + 2 * ip;
            int mB = mA + 1;
            if (mA < M) {
                float v = v0 + bsv;
                if (relu) v = fmaxf(v, 0.f);
                C[(size_t)mA * N + n] = v;
            }
            if (mB < M) {
                float v = v1 + bsv;
                if (relu) v = fmaxf(v, 0.f);
                C[(size_t)mB * N + n] = v;
            }
        }
    }
}

// ---------------- GRU scan: weights in registers, FFMA2 ----------------
// grid = 128 blocks (dir*64+b), 384 threads (one per gate unit).
__global__ void __launch_bounds__(G3, 1)
gru_kernel(const float* __restrict__ xg,    // [B*S][768]
           const float* __restrict__ w_hh,  // [2][384][128]
           const float* __restrict__ b_hh,  // [2][384]
           const int* __restrict__ lens,
           float* __restrict__ out) {       // [B*S][256]
    __shared__ float sh_h[Hn];
    __shared__ float sh_hg[G3];
    int g = threadIdx.x;
    int dir = blockIdx.x / Bn;
    int b = blockIdx.x % Bn;

    // load this gate's 128 weights into registers as 64 f32x2 pairs
    ull wr2[64];
    {
        const ulonglong2* Wrow = (const ulonglong2*)(w_hh + (size_t)dir * G3 * Hn + (size_t)g * Hn);
#pragma unroll
        for (int i = 0; i < 32; ++i) {
            ulonglong2 v = Wrow[i];
            wr2[2 * i] = v.x;
            wr2[2 * i + 1] = v.y;
        }
    }
    if (g < Hn) sh_h[g] = 0.f;
    float bh = b_hh[dir * G3 + g];
    int len = lens[b];
    const float* xgb = xg + (size_t)b * Sn * G6 + dir * G3;
    float* outb = out + (size_t)b * Sn * 256 + dir * Hn;
    __syncthreads();

    const ulonglong2* h2 = (const ulonglong2*)sh_h;   // broadcast reads
    for (int t = 0; t < Sn; ++t) {
        int s = dir ? (Sn - 1 - t) : t;
        // prefetch gate inputs (hidden under the matvec below)
        float xr = 0.f, xz = 0.f, xn = 0.f;
        if (g < Hn) {
            const float* xs = xgb + (size_t)s * G6;
            xr = xs[g]; xz = xs[Hn + g]; xn = xs[2 * Hn + g];
        }
        // h @ W_hh^T : 64 FFMA2 per thread
        ull a0 = pk2(0.f, 0.f), a1 = a0, a2 = a0, a3 = a0;
#pragma unroll
        for (int i = 0; i < 16; ++i) {
            ulonglong2 hA = h2[2 * i];
            ulonglong2 hB = h2[2 * i + 1];
            ffma2(a0, wr2[4 * i + 0], hA.x);
            ffma2(a1, wr2[4 * i + 1], hA.y);
            ffma2(a2, wr2[4 * i + 2], hB.x);
            ffma2(a3, wr2[4 * i + 3], hB.y);
        }
        float l0, h0v, l1, h1v, l2, h2v, l3, h3v;
        upk2(a0, l0, h0v); upk2(a1, l1, h1v);
        upk2(a2, l2, h2v); upk2(a3, l3, h3v);
        sh_hg[g] = bh + (((l0 + h0v) + (l1 + h1v)) + ((l2 + h2v) + (l3 + h3v)));
        __syncthreads();
        if (g < Hn) {
            float hr = sh_hg[g], hz = sh_hg[Hn + g], hn = sh_hg[2 * Hn + g];
            float r = 1.f / (1.f + expf(-(xr + hr)));
            float z = 1.f / (1.f + expf(-(xz + hz)));
            float n = tanhf(xn + r * hn);
            float hp = sh_h[g];
            float hv = (s < len) ? ((1.f - z) * n + z * hp) : hp;
            sh_h[g] = hv;
            outb[(size_t)s * 256 + g] = hv;
        }
        __syncthreads();
    }
}

// ---------------- CRF ----------------
__global__ void crf_kernel(const float* __restrict__ start,
                           const float* __restrict__ end_,
                           const float* __restrict__ trans,
                           const int* __restrict__ target,
                           const int* __restrict__ lens) {
    int b = blockIdx.x, lane = threadIdx.x;
    const float* E = g_emis + (size_t)b * Sn * Tn;
    const int* tgt = target + b * Sn;
    int len = lens[b];

    float partial = 0.f;
    for (int s = 1 + lane; s < Sn; s += 32) {
        if (s < len)
            partial += trans[tgt[s - 1] * Tn + tgt[s]] + E[s * Tn + tgt[s]];
    }
#pragma unroll
    for (int o = 16; o; o >>= 1) partial += __shfl_down_sync(0xffffffffu, partial, o);

    float tc[Tn];
    float alpha = -1e30f;
    if (lane < Tn) {
        alpha = start[lane] + E[lane];
#pragma unroll
        for (int i = 0; i < Tn; ++i) tc[i] = trans[i * Tn + lane];
    } else {
#pragma unroll
        for (int i = 0; i < Tn; ++i) tc[i] = 0.f;
    }
    for (int s = 1; s < Sn; ++s) {
        float av[Tn];
        float mx = -1e30f;
#pragma unroll
        for (int i = 0; i < Tn; ++i) {
            av[i] = __shfl_sync(0xffffffffu, alpha, i) + tc[i];
            mx = fmaxf(mx, av[i]);
        }
        float sum = 0.f;
#pragma unroll
        for (int i = 0; i < Tn; ++i) sum += expf(av[i] - mx);
        float e = (lane < Tn) ? E[s * Tn + lane] : 0.f;
        float nw = mx + logf(sum) + e;
        if (lane < Tn && s < len) alpha = nw;
    }
    float v = (lane < Tn) ? alpha + end_[lane] : -1e30f;
    float mx = v;
#pragma unroll
    for (int o = 16; o; o >>= 1) mx = fmaxf(mx, __shfl_xor_sync(0xffffffffu, mx, o));
    float se = expf(v - mx);
#pragma unroll
    for (int o = 16; o; o >>= 1) se += __shfl_xor_sync(0xffffffffu, se, o);
    float logz = mx + logf(se);
    if (lane == 0) {
        float score = partial + start[tgt[0]] + E[tgt[0]] + end_[tgt[len - 1]];
        g_llh[b] = score - logz;
    }
}

__global__ void finalize_kernel(const int* __restrict__ lens, float* __restrict__ out) {
    float sl = 0.f;
    float smk = 0.f;
    for (int b = 0; b < Bn; ++b) { sl += g_llh[b]; smk += (float)lens[b]; }
    out[0] = -sl / smk;
}

// ---------------- launch ----------------
extern "C" void kernel_launch(void* const* d_in, const int* in_sizes, int n_in,
                              void* d_out, int out_size) {
    const float* char_emb  = (const float*)d_in[0];
    const float* conv_w    = (const float*)d_in[1];
    const float* conv_b    = (const float*)d_in[2];
    const float* word_emb  = (const float*)d_in[3];
    const float* w_ih_l0   = (const float*)d_in[4];
    const float* w_hh_l0   = (const float*)d_in[5];
    const float* b_ih_l0   = (const float*)d_in[6];
    const float* b_hh_l0   = (const float*)d_in[7];
    const float* w_ih_l1   = (const float*)d_in[8];
    const float* w_hh_l1   = (const float*)d_in[9];
    const float* b_ih_l1   = (const float*)d_in[10];
    const float* b_hh_l1   = (const float*)d_in[11];
    const float* mlp_w1    = (const float*)d_in[12];
    const float* mlp_b1    = (const float*)d_in[13];
    const float* mlp_w2    = (const float*)d_in[14];
    const float* mlp_b2    = (const float*)d_in[15];
    const float* crf_start = (const float*)d_in[16];
    const float* crf_end   = (const float*)d_in[17];
    const float* crf_trans = (const float*)d_in[18];
    const int* char_words  = (const int*)d_in[19];
    const int* cwi         = (const int*)d_in[21];
    const int* tokens      = (const int*)d_in[22];
    const int* tokens_len  = (const int*)d_in[23];
    const int* target      = (const int*)d_in[24];
    float* out = (float*)d_out;

    void* pv;
    cudaGetSymbolAddress(&pv, g_texts); float* p_texts = (float*)pv;
    cudaGetSymbolAddress(&pv, g_xg);    float* p_xg    = (float*)pv;
    cudaGetSymbolAddress(&pv, g_h0);    float* p_h0    = (float*)pv;
    cudaGetSymbolAddress(&pv, g_h1);    float* p_h1    = (float*)pv;
    cudaGetSymbolAddress(&pv, g_mlp);   float* p_mlp   = (float*)pv;
    cudaGetSymbolAddress(&pv, g_emis);  float* p_emis  = (float*)pv;

    const int M = Bn * Sn;  // 16384

    char_cnn_kernel<<<NWn + 1, 480>>>(char_emb, conv_w, conv_b, char_words);
    build_texts_kernel<<<M, 352>>>(word_emb, tokens, cwi);
    gemm_kernel<<<dim3(G6 / 64, M / 128), 256>>>(p_texts, w_ih_l0, b_ih_l0, p_xg,
                                                 M, G6, INW0, 0, 1);
    gru_kernel<<<2 * Bn, G3>>>(p_xg, w_hh_l0, b_hh_l0, tokens_len, p_h0);
    gemm_kernel<<<dim3(G6 / 64, M / 128), 256>>>(p_h0, w_ih_l1, b_ih_l1, p_xg,
                                                 M, G6, 256, 0, 1);
    gru_kernel<<<2 * Bn, G3>>>(p_xg, w_hh_l1, b_hh_l1, tokens_len, p_h1);
    gemm_kernel<<<dim3(Hn / 64, M / 128), 256>>>(p_h1, mlp_w1, mlp_b1, p_mlp,
                                                 M, Hn, 256, 1, 0);
    gemm_kernel<<<dim3(1, M / 128), 256>>>(p_mlp, mlp_w2, mlp_b2, p_emis,
                                           M, Tn, Hn, 0, 0);
    crf_kernel<<<Bn, 32>>>(crf_start, crf_end, crf_trans, target, tokens_len);
    finalize_kernel<<<1, 1>>>(tokens_len, out);
}

// round 4
// speedup vs baseline: 1.8012x; 1.2863x over previous
#include <cuda_runtime.h>
#include <math.h>

// Problem constants
#define Bn   64
#define Sn   256
#define Dn   300
#define NWn  8192
#define CLn  16
#define CDn  30
#define CHn  30
#define Hn   128
#define Tn   17
#define INW0 330   // D + CH
#define G3   384   // 3*H
#define G6   768   // 2 dirs * 3H

typedef unsigned long long ull;

// ---------------- f32x2 helpers (FFMA2) ----------------
__device__ __forceinline__ ull pk2(float lo, float hi) {
    ull r; asm("mov.b64 %0,{%1,%2};" : "=l"(r) : "f"(lo), "f"(hi)); return r;
}
__device__ __forceinline__ void ffma2(ull& acc, ull a, ull b) {
    asm("fma.rn.f32x2 %0,%1,%2,%0;" : "+l"(acc) : "l"(a), "l"(b));
}
__device__ __forceinline__ void upk2(ull v, float& lo, float& hi) {
    asm("mov.b64 {%0,%1},%2;" : "=f"(lo), "=f"(hi) : "l"(v));
}

__device__ __forceinline__ float fast_sigmoid(float v) {
    float e = __expf(-v);
    return __fdividef(1.f, 1.f + e);
}
__device__ __forceinline__ float fast_tanh(float v) {
    v = fminf(fmaxf(v, -10.f), 10.f);
    float e2 = __expf(2.f * v);
    return __fdividef(e2 - 1.f, e2 + 1.f);
}

// ---------------- device scratch (static, no allocation) ----------------
__device__ float g_tokenc[(NWn + 1) * CHn];
__device__ float g_texts[(size_t)Bn * Sn * INW0];
__device__ float g_xg[(size_t)Bn * Sn * G6];
__device__ float g_h0[(size_t)Bn * Sn * 256];
__device__ float g_h1[(size_t)Bn * Sn * 256];
__device__ float g_mlp[(size_t)Bn * Sn * Hn];
__device__ float g_emis[(size_t)Bn * Sn * Tn + 64];
__device__ float g_llh[Bn];

// ---------------- char CNN ----------------
__global__ void char_cnn_kernel(const float* __restrict__ char_emb,
                                const float* __restrict__ conv_w,
                                const float* __restrict__ conv_b,
                                const int* __restrict__ words) {
    __shared__ float s_emb[CLn + 2][CDn];
    __shared__ float s_w[CHn * CDn * 3];
    __shared__ float s_out[CHn * CLn];
    __shared__ int   s_idx[CLn];
    int tid = threadIdx.x;
    int blk = blockIdx.x;
    if (blk == 0) {
        if (tid < CHn) g_tokenc[tid] = 0.f;
        return;
    }
    int w = blk - 1;
    if (tid < CLn) s_idx[tid] = words[w * CLn + tid];
    for (int i = tid; i < CHn * CDn * 3; i += blockDim.x) s_w[i] = conv_w[i];
    if (tid < CDn) { s_emb[0][tid] = 0.f; s_emb[CLn + 1][tid] = 0.f; }
    __syncthreads();
    if (tid < CLn * CDn) {
        int t = tid / CDn, d = tid % CDn;
        s_emb[t + 1][d] = char_emb[s_idx[t] * CDn + d];
    }
    __syncthreads();
    {
        int ch = tid / CLn, t = tid % CLn;
        float acc = conv_b[ch];
        const float* wr = &s_w[ch * CDn * 3];
#pragma unroll
        for (int d = 0; d < CDn; ++d) {
            acc += s_emb[t][d]     * wr[d * 3 + 0];
            acc += s_emb[t + 1][d] * wr[d * 3 + 1];
            acc += s_emb[t + 2][d] * wr[d * 3 + 2];
        }
        s_out[ch * CLn + t] = fmaxf(acc, 0.f);
    }
    __syncthreads();
    if (tid < CHn) {
        float m = s_out[tid * CLn];
#pragma unroll
        for (int t = 1; t < CLn; ++t) m = fmaxf(m, s_out[tid * CLn + t]);
        g_tokenc[(w + 1) * CHn + tid] = m;
    }
}

// ---------------- build texts ----------------
__global__ void build_texts_kernel(const float* __restrict__ word_emb,
                                   const int* __restrict__ tokens,
                                   const int* __restrict__ cwi) {
    int m = blockIdx.x;
    int tid = threadIdx.x;
    int tok = tokens[m];
    int ci = cwi[m];
    if (tid < Dn)
        g_texts[(size_t)m * INW0 + tid] = word_emb[(size_t)tok * Dn + tid];
    else if (tid < INW0)
        g_texts[(size_t)m * INW0 + tid] = g_tokenc[ci * CHn + (tid - Dn)];
}

// ---------------- SGEMM 128x64 tile, 8x4 per thread (scalar, R2 proven) ----------------
__global__ void gemm_kernel(const float* __restrict__ A,
                            const float* __restrict__ W,
                            const float* __restrict__ bias,
                            float* __restrict__ C,
                            int M, int N, int K, int relu, int wNK) {
    __shared__ float As[16][129];
    __shared__ float Ws[16][65];
    int tid = threadIdx.x;
    int tx = tid % 16, ty = tid / 16;
    int m0 = blockIdx.y * 128, n0 = blockIdx.x * 64;
    float acc[8][4] = {};
    int ktiles = (K + 15) / 16;
    for (int kt = 0; kt < ktiles; ++kt) {
        int k0 = kt * 16;
#pragma unroll
        for (int l = 0; l < 8; ++l) {             // A tile: 128x16
            int e = tid + l * 256;
            int kk = e % 16, i = e / 16;
            int m = m0 + i, k = k0 + kk;
            As[kk][i] = (k < K && m < M) ? A[(size_t)m * K + k] : 0.f;
        }
#pragma unroll
        for (int l = 0; l < 4; ++l) {             // W tile: 64x16
            int e = tid + l * 256;
            int kk = e % 16, i = e / 16;
            int n = n0 + i, k = k0 + kk;
            float wv = 0.f;
            if (k < K && n < N)
                wv = wNK ? W[(size_t)n * K + k] : W[(size_t)k * N + n];
            Ws[kk][i] = wv;
        }
        __syncthreads();
#pragma unroll
        for (int kk = 0; kk < 16; ++kk) {
            float a[8], b[4];
#pragma unroll
            for (int i = 0; i < 8; ++i) a[i] = As[kk][ty * 8 + i];
#pragma unroll
            for (int j = 0; j < 4; ++j) b[j] = Ws[kk][tx * 4 + j];
#pragma unroll
            for (int i = 0; i < 8; ++i)
#pragma unroll
                for (int j = 0; j < 4; ++j)
                    acc[i][j] += a[i] * b[j];
        }
        __syncthreads();
    }
#pragma unroll
    for (int i = 0; i < 8; ++i) {
        int m = m0 + ty * 8 + i;
        if (m >= M) continue;
#pragma unroll
        for (int j = 0; j < 4; ++j) {
            int n = n0 + tx * 4 + j;
            if (n >= N) continue;
            float v = acc[i][j] + bias[n];
            if (relu) v = fmaxf(v, 0.f);
            C[(size_t)m * N + n] = v;
        }
    }
}

// ---------------- GRU scan: K-split x2, 768 threads, weights in regs ----------------
#define GT 768
__global__ void __launch_bounds__(GT, 1)
gru_kernel(const float* __restrict__ xg,    // [B*S][768]
           const float* __restrict__ w_hh,  // [2][384][128]
           const float* __restrict__ b_hh,  // [2][384]
           const int* __restrict__ lens,
           float* __restrict__ out) {       // [B*S][256]
    __shared__ float sh_h[Hn];
    __shared__ float sh_part[2 * G3];
    __shared__ float sh_x[G3];
    int tid = threadIdx.x;
    int ks = (tid >= G3) ? 1 : 0;
    int g = tid - ks * G3;
    int dir = blockIdx.x / Bn;
    int b = blockIdx.x % Bn;

    // this thread's 64-weight K-slice, packed f32x2
    ull wr2[32];
    {
        const ulonglong2* Wrow =
            (const ulonglong2*)(w_hh + (size_t)dir * G3 * Hn + (size_t)g * Hn + ks * 64);
#pragma unroll
        for (int i = 0; i < 16; ++i) {
            ulonglong2 v = Wrow[i];
            wr2[2 * i] = v.x;
            wr2[2 * i + 1] = v.y;
        }
    }
    if (tid < Hn) sh_h[tid] = 0.f;
    float bh = ks ? 0.f : b_hh[dir * G3 + g];
    int len = lens[b];
    const float* xgb = xg + (size_t)b * Sn * G6 + dir * G3;
    float* outb = out + (size_t)b * Sn * 256 + dir * Hn;
    __syncthreads();

    const ulonglong2* h2 = (const ulonglong2*)(sh_h + ks * 64);
    for (int t = 0; t < Sn; ++t) {
        int s = dir ? (Sn - 1 - t) : t;
        // ks=1 warps stage this step's gate inputs into smem (overlaps matvec)
        if (ks) sh_x[g] = xgb[(size_t)s * G6 + g];
        // 64-wide partial dot: 32 FFMA2
        ull a0 = pk2(0.f, 0.f), a1 = a0;
#pragma unroll
        for (int i = 0; i < 8; ++i) {
            ulonglong2 hA = h2[2 * i];
            ulonglong2 hB = h2[2 * i + 1];
            ffma2(a0, wr2[4 * i + 0], hA.x);
            ffma2(a1, wr2[4 * i + 1], hA.y);
            ffma2(a0, wr2[4 * i + 2], hB.x);
            ffma2(a1, wr2[4 * i + 3], hB.y);
        }
        float l0, h0v, l1, h1v;
        upk2(a0, l0, h0v); upk2(a1, l1, h1v);
        sh_part[ks * G3 + g] = bh + ((l0 + h0v) + (l1 + h1v));
        __syncthreads();
        if (tid < Hn) {
            float xr = sh_x[tid], xz = sh_x[Hn + tid], xn = sh_x[2 * Hn + tid];
            float hr = sh_part[tid] + sh_part[G3 + tid];
            float hz = sh_part[Hn + tid] + sh_part[G3 + Hn + tid];
            float hnv = sh_part[2 * Hn + tid] + sh_part[G3 + 2 * Hn + tid];
            float r = fast_sigmoid(xr + hr);
            float z = fast_sigmoid(xz + hz);
            float n = fast_tanh(xn + r * hnv);
            float hp = sh_h[tid];
            float hv = (s < len) ? ((1.f - z) * n + z * hp) : hp;
            sh_h[tid] = hv;
            outb[(size_t)s * 256 + tid] = hv;
        }
        __syncthreads();
    }
}

// ---------------- CRF ----------------
__global__ void crf_kernel(const float* __restrict__ start,
                           const float* __restrict__ end_,
                           const float* __restrict__ trans,
                           const int* __restrict__ target,
                           const int* __restrict__ lens) {
    int b = blockIdx.x, lane = threadIdx.x;
    const float* E = g_emis + (size_t)b * Sn * Tn;
    const int* tgt = target + b * Sn;
    int len = lens[b];

    float partial = 0.f;
    for (int s = 1 + lane; s < Sn; s += 32) {
        if (s < len)
            partial += trans[tgt[s - 1] * Tn + tgt[s]] + E[s * Tn + tgt[s]];
    }
#pragma unroll
    for (int o = 16; o; o >>= 1) partial += __shfl_down_sync(0xffffffffu, partial, o);

    float tc[Tn];
    float alpha = -1e30f;
    if (lane < Tn) {
        alpha = start[lane] + E[lane];
#pragma unroll
        for (int i = 0; i < Tn; ++i) tc[i] = trans[i * Tn + lane];
    } else {
#pragma unroll
        for (int i = 0; i < Tn; ++i) tc[i] = 0.f;
    }
    for (int s = 1; s < Sn; ++s) {
        float av[Tn];
        float mx = -1e30f;
#pragma unroll
        for (int i = 0; i < Tn; ++i) {
            av[i] = __shfl_sync(0xffffffffu, alpha, i) + tc[i];
            mx = fmaxf(mx, av[i]);
        }
        float sum = 0.f;
#pragma unroll
        for (int i = 0; i < Tn; ++i) sum += expf(av[i] - mx);
        float e = (lane < Tn) ? E[s * Tn + lane] : 0.f;
        float nw = mx + logf(sum) + e;
        if (lane < Tn && s < len) alpha = nw;
    }
    float v = (lane < Tn) ? alpha + end_[lane] : -1e30f;
    float mx = v;
#pragma unroll
    for (int o = 16; o; o >>= 1) mx = fmaxf(mx, __shfl_xor_sync(0xffffffffu, mx, o));
    float se = expf(v - mx);
#pragma unroll
    for (int o = 16; o; o >>= 1) se += __shfl_xor_sync(0xffffffffu, se, o);
    float logz = mx + logf(se);
    if (lane == 0) {
        float score = partial + start[tgt[0]] + E[tgt[0]] + end_[tgt[len - 1]];
        g_llh[b] = score - logz;
    }
}

__global__ void finalize_kernel(const int* __restrict__ lens, float* __restrict__ out) {
    float sl = 0.f;
    float smk = 0.f;
    for (int b = 0; b < Bn; ++b) { sl += g_llh[b]; smk += (float)lens[b]; }
    out[0] = -sl / smk;
}

// ---------------- launch ----------------
extern "C" void kernel_launch(void* const* d_in, const int* in_sizes, int n_in,
                              void* d_out, int out_size) {
    const float* char_emb  = (const float*)d_in[0];
    const float* conv_w    = (const float*)d_in[1];
    const float* conv_b    = (const float*)d_in[2];
    const float* word_emb  = (const float*)d_in[3];
    const float* w_ih_l0   = (const float*)d_in[4];
    const float* w_hh_l0   = (const float*)d_in[5];
    const float* b_ih_l0   = (const float*)d_in[6];
    const float* b_hh_l0   = (const float*)d_in[7];
    const float* w_ih_l1   = (const float*)d_in[8];
    const float* w_hh_l1   = (const float*)d_in[9];
    const float* b_ih_l1   = (const float*)d_in[10];
    const float* b_hh_l1   = (const float*)d_in[11];
    const float* mlp_w1    = (const float*)d_in[12];
    const float* mlp_b1    = (const float*)d_in[13];
    const float* mlp_w2    = (const float*)d_in[14];
    const float* mlp_b2    = (const float*)d_in[15];
    const float* crf_start = (const float*)d_in[16];
    const float* crf_end   = (const float*)d_in[17];
    const float* crf_trans = (const float*)d_in[18];
    const int* char_words  = (const int*)d_in[19];
    const int* cwi         = (const int*)d_in[21];
    const int* tokens      = (const int*)d_in[22];
    const int* tokens_len  = (const int*)d_in[23];
    const int* target      = (const int*)d_in[24];
    float* out = (float*)d_out;

    void* pv;
    cudaGetSymbolAddress(&pv, g_texts); float* p_texts = (float*)pv;
    cudaGetSymbolAddress(&pv, g_xg);    float* p_xg    = (float*)pv;
    cudaGetSymbolAddress(&pv, g_h0);    float* p_h0    = (float*)pv;
    cudaGetSymbolAddress(&pv, g_h1);    float* p_h1    = (float*)pv;
    cudaGetSymbolAddress(&pv, g_mlp);   float* p_mlp   = (float*)pv;
    cudaGetSymbolAddress(&pv, g_emis);  float* p_emis  = (float*)pv;

    const int M = Bn * Sn;  // 16384

    char_cnn_kernel<<<NWn + 1, 480>>>(char_emb, conv_w, conv_b, char_words);
    build_texts_kernel<<<M, 352>>>(word_emb, tokens, cwi);
    gemm_kernel<<<dim3(G6 / 64, M / 128), 256>>>(p_texts, w_ih_l0, b_ih_l0, p_xg,
                                                 M, G6, INW0, 0, 1);
    gru_kernel<<<2 * Bn, GT>>>(p_xg, w_hh_l0, b_hh_l0, tokens_len, p_h0);
    gemm_kernel<<<dim3(G6 / 64, M / 128), 256>>>(p_h0, w_ih_l1, b_ih_l1, p_xg,
                                                 M, G6, 256, 0, 1);
    gru_kernel<<<2 * Bn, GT>>>(p_xg, w_hh_l1, b_hh_l1, tokens_len, p_h1);
    gemm_kernel<<<dim3(Hn / 64, M / 128), 256>>>(p_h1, mlp_w1, mlp_b1, p_mlp,
                                                 M, Hn, 256, 1, 0);
    gemm_kernel<<<dim3(1, M / 128), 256>>>(p_mlp, mlp_w2, mlp_b2, p_emis,
                                           M, Tn, Hn, 0, 0);
    crf_kernel<<<Bn, 32>>>(crf_start, crf_end, crf_trans, target, tokens_len);
    finalize_kernel<<<1, 1>>>(tokens_len, out);
}

// round 5
// speedup vs baseline: 1.8287x; 1.0153x over previous
#include <cuda_runtime.h>
#include <math.h>

// Problem constants
#define Bn   64
#define Sn   256
#define Dn   300
#define NWn  8192
#define CLn  16
#define CDn  30
#define CHn  30
#define Hn   128
#define Tn   17
#define INW0 330   // D + CH
#define G3   384   // 3*H
#define G6   768   // 2 dirs * 3H

typedef unsigned long long ull;

// ---------------- f32x2 / fast-math helpers ----------------
__device__ __forceinline__ ull pk2(float lo, float hi) {
    ull r; asm("mov.b64 %0,{%1,%2};" : "=l"(r) : "f"(lo), "f"(hi)); return r;
}
__device__ __forceinline__ void ffma2(ull& acc, ull a, ull b) {
    asm("fma.rn.f32x2 %0,%1,%2,%0;" : "+l"(acc) : "l"(a), "l"(b));
}
__device__ __forceinline__ void upk2(ull v, float& lo, float& hi) {
    asm("mov.b64 {%0,%1},%2;" : "=f"(lo), "=f"(hi) : "l"(v));
}
__device__ __forceinline__ float tanh_fast(float v) {
    float r; asm("tanh.approx.f32 %0,%1;" : "=f"(r) : "f"(v)); return r;
}
__device__ __forceinline__ float sigmoid_fast(float v) {
    return fmaf(tanh_fast(0.5f * v), 0.5f, 0.5f);
}

// ---------------- device scratch (static, no allocation) ----------------
__device__ float g_tokenc[(NWn + 1) * CHn];
__device__ float g_texts[(size_t)Bn * Sn * INW0];
__device__ float g_xg[(size_t)Bn * Sn * G6];
__device__ float g_h0[(size_t)Bn * Sn * 256];
__device__ float g_h1[(size_t)Bn * Sn * 256];
__device__ float g_mlp[(size_t)Bn * Sn * Hn];
__device__ float g_emis[(size_t)Bn * Sn * Tn + 64];
__device__ float g_llh[Bn];

// ---------------- char CNN ----------------
__global__ void char_cnn_kernel(const float* __restrict__ char_emb,
                                const float* __restrict__ conv_w,
                                const float* __restrict__ conv_b,
                                const int* __restrict__ words) {
    __shared__ float s_emb[CLn + 2][CDn];
    __shared__ float s_w[CHn * CDn * 3];
    __shared__ float s_out[CHn * CLn];
    __shared__ int   s_idx[CLn];
    int tid = threadIdx.x;
    int blk = blockIdx.x;
    if (blk == 0) {
        if (tid < CHn) g_tokenc[tid] = 0.f;
        return;
    }
    int w = blk - 1;
    if (tid < CLn) s_idx[tid] = words[w * CLn + tid];
    for (int i = tid; i < CHn * CDn * 3; i += blockDim.x) s_w[i] = conv_w[i];
    if (tid < CDn) { s_emb[0][tid] = 0.f; s_emb[CLn + 1][tid] = 0.f; }
    __syncthreads();
    if (tid < CLn * CDn) {
        int t = tid / CDn, d = tid % CDn;
        s_emb[t + 1][d] = char_emb[s_idx[t] * CDn + d];
    }
    __syncthreads();
    {
        int ch = tid / CLn, t = tid % CLn;
        float acc = conv_b[ch];
        const float* wr = &s_w[ch * CDn * 3];
#pragma unroll
        for (int d = 0; d < CDn; ++d) {
            acc += s_emb[t][d]     * wr[d * 3 + 0];
            acc += s_emb[t + 1][d] * wr[d * 3 + 1];
            acc += s_emb[t + 2][d] * wr[d * 3 + 2];
        }
        s_out[ch * CLn + t] = fmaxf(acc, 0.f);
    }
    __syncthreads();
    if (tid < CHn) {
        float m = s_out[tid * CLn];
#pragma unroll
        for (int t = 1; t < CLn; ++t) m = fmaxf(m, s_out[tid * CLn + t]);
        g_tokenc[(w + 1) * CHn + tid] = m;
    }
}

// ---------------- build texts ----------------
__global__ void build_texts_kernel(const float* __restrict__ word_emb,
                                   const int* __restrict__ tokens,
                                   const int* __restrict__ cwi) {
    int m = blockIdx.x;
    int tid = threadIdx.x;
    int tok = tokens[m];
    int ci = cwi[m];
    if (tid < Dn)
        g_texts[(size_t)m * INW0 + tid] = word_emb[(size_t)tok * Dn + tid];
    else if (tid < INW0)
        g_texts[(size_t)m * INW0 + tid] = g_tokenc[ci * CHn + (tid - Dn)];
}

// ---------------- SGEMM 128x128 tile, 8x8 per thread, 256 threads ----------------
// C[M][N] = A[M][K] * W(+bias); wNK=1: W is [N][K]; wNK=0: W is [K][N].
__global__ void __launch_bounds__(256)
gemm_kernel(const float* __restrict__ A,
            const float* __restrict__ W,
            const float* __restrict__ bias,
            float* __restrict__ C,
            int M, int N, int K, int relu, int wNK) {
    __shared__ float As[16][132];
    __shared__ float Ws[16][132];
    int tid = threadIdx.x;
    int tx = tid % 16, ty = tid / 16;
    int m0 = blockIdx.y * 128, n0 = blockIdx.x * 128;
    float acc[8][8] = {};
    int ktiles = (K + 15) / 16;
    for (int kt = 0; kt < ktiles; ++kt) {
        int k0 = kt * 16;
#pragma unroll
        for (int l = 0; l < 8; ++l) {             // A tile: 128 rows x 16 k
            int e = tid + l * 256;
            int kk = e % 16, i = e / 16;
            int m = m0 + i, k = k0 + kk;
            As[kk][i] = (k < K && m < M) ? A[(size_t)m * K + k] : 0.f;
        }
#pragma unroll
        for (int l = 0; l < 8; ++l) {             // W tile: 128 cols x 16 k
            int e = tid + l * 256;
            int kk = e % 16, i = e / 16;
            int n = n0 + i, k = k0 + kk;
            float wv = 0.f;
            if (k < K && n < N)
                wv = wNK ? W[(size_t)n * K + k] : W[(size_t)k * N + n];
            Ws[kk][i] = wv;
        }
        __syncthreads();
#pragma unroll
        for (int kk = 0; kk < 16; ++kk) {
            float4 a0 = *(const float4*)&As[kk][ty * 8];
            float4 a1 = *(const float4*)&As[kk][ty * 8 + 4];
            float4 b0 = *(const float4*)&Ws[kk][tx * 8];
            float4 b1 = *(const float4*)&Ws[kk][tx * 8 + 4];
            float a[8] = {a0.x, a0.y, a0.z, a0.w, a1.x, a1.y, a1.z, a1.w};
            float b[8] = {b0.x, b0.y, b0.z, b0.w, b1.x, b1.y, b1.z, b1.w};
#pragma unroll
            for (int i = 0; i < 8; ++i)
#pragma unroll
                for (int j = 0; j < 8; ++j)
                    acc[i][j] += a[i] * b[j];
        }
        __syncthreads();
    }
#pragma unroll
    for (int i = 0; i < 8; ++i) {
        int m = m0 + ty * 8 + i;
        if (m >= M) continue;
#pragma unroll
        for (int j = 0; j < 8; ++j) {
            int n = n0 + tx * 8 + j;
            if (n >= N) continue;
            float v = acc[i][j] + bias[n];
            if (relu) v = fmaxf(v, 0.f);
            C[(size_t)m * N + n] = v;
        }
    }
}

// ---------------- GRU scan: K-split x2, x prefetched a full step ahead ----------------
#define GT 768
__global__ void __launch_bounds__(GT, 1)
gru_kernel(const float* __restrict__ xg,    // [B*S][768]
           const float* __restrict__ w_hh,  // [2][384][128]
           const float* __restrict__ b_hh,  // [2][384]
           const int* __restrict__ lens,
           float* __restrict__ out) {       // [B*S][256]
    __shared__ float sh_h[Hn];
    __shared__ float sh_part[2 * G3];
    __shared__ float sh_x[G3];
    int tid = threadIdx.x;
    int ks = (tid >= G3) ? 1 : 0;
    int g = tid - ks * G3;
    int dir = blockIdx.x / Bn;
    int b = blockIdx.x % Bn;

    // this thread's 64-weight K-slice, packed f32x2
    ull wr2[32];
    {
        const ulonglong2* Wrow =
            (const ulonglong2*)(w_hh + (size_t)dir * G3 * Hn + (size_t)g * Hn + ks * 64);
#pragma unroll
        for (int i = 0; i < 16; ++i) {
            ulonglong2 v = Wrow[i];
            wr2[2 * i] = v.x;
            wr2[2 * i + 1] = v.y;
        }
    }
    if (tid < Hn) sh_h[tid] = 0.f;
    float bh = ks ? 0.f : b_hh[dir * G3 + g];
    int len = lens[b];
    const float* xgb = xg + (size_t)b * Sn * G6 + dir * G3;
    float* outb = out + (size_t)b * Sn * 256 + dir * Hn;

    // prime the x pipeline: ks=1 threads hold step-0's x value in a register
    float xnext = 0.f;
    if (ks) {
        int s0 = dir ? (Sn - 1) : 0;
        xnext = xgb[(size_t)s0 * G6 + g];
    }
    __syncthreads();

    const ulonglong2* h2 = (const ulonglong2*)(sh_h + ks * 64);
    for (int t = 0; t < Sn; ++t) {
        int s = dir ? (Sn - 1 - t) : t;
        if (ks) {
            sh_x[g] = xnext;                       // already-arrived data
            if (t + 1 < Sn) {                      // issue next step's load now
                int sn = dir ? (s - 1) : (s + 1);
                xnext = xgb[(size_t)sn * G6 + g];
            }
        }
        // 64-wide partial dot: 32 FFMA2
        ull a0 = pk2(0.f, 0.f), a1 = a0;
#pragma unroll
        for (int i = 0; i < 8; ++i) {
            ulonglong2 hA = h2[2 * i];
            ulonglong2 hB = h2[2 * i + 1];
            ffma2(a0, wr2[4 * i + 0], hA.x);
            ffma2(a1, wr2[4 * i + 1], hA.y);
            ffma2(a0, wr2[4 * i + 2], hB.x);
            ffma2(a1, wr2[4 * i + 3], hB.y);
        }
        float l0, h0v, l1, h1v;
        upk2(a0, l0, h0v); upk2(a1, l1, h1v);
        sh_part[ks * G3 + g] = bh + ((l0 + h0v) + (l1 + h1v));
        __syncthreads();
        if (tid < Hn) {
            float xr = sh_x[tid], xz = sh_x[Hn + tid], xn = sh_x[2 * Hn + tid];
            float hr = sh_part[tid] + sh_part[G3 + tid];
            float hz = sh_part[Hn + tid] + sh_part[G3 + Hn + tid];
            float hnv = sh_part[2 * Hn + tid] + sh_part[G3 + 2 * Hn + tid];
            float r = sigmoid_fast(xr + hr);
            float z = sigmoid_fast(xz + hz);
            float n = tanh_fast(fmaf(r, hnv, xn));
            float hp = sh_h[tid];
            float hv = (s < len) ? ((1.f - z) * n + z * hp) : hp;
            sh_h[tid] = hv;
            outb[(size_t)s * 256 + tid] = hv;
        }
        __syncthreads();
    }
}

// ---------------- CRF ----------------
__global__ void crf_kernel(const float* __restrict__ start,
                           const float* __restrict__ end_,
                           const float* __restrict__ trans,
                           const int* __restrict__ target,
                           const int* __restrict__ lens) {
    int b = blockIdx.x, lane = threadIdx.x;
    const float* E = g_emis + (size_t)b * Sn * Tn;
    const int* tgt = target + b * Sn;
    int len = lens[b];

    float partial = 0.f;
    for (int s = 1 + lane; s < Sn; s += 32) {
        if (s < len)
            partial += trans[tgt[s - 1] * Tn + tgt[s]] + E[s * Tn + tgt[s]];
    }
#pragma unroll
    for (int o = 16; o; o >>= 1) partial += __shfl_down_sync(0xffffffffu, partial, o);

    float tc[Tn];
    float alpha = -1e30f;
    if (lane < Tn) {
        alpha = start[lane] + E[lane];
#pragma unroll
        for (int i = 0; i < Tn; ++i) tc[i] = trans[i * Tn + lane];
    } else {
#pragma unroll
        for (int i = 0; i < Tn; ++i) tc[i] = 0.f;
    }
    for (int s = 1; s < Sn; ++s) {
        float av[Tn];
        float mx = -1e30f;
#pragma unroll
        for (int i = 0; i < Tn; ++i) {
            av[i] = __shfl_sync(0xffffffffu, alpha, i) + tc[i];
            mx = fmaxf(mx, av[i]);
        }
        float sum = 0.f;
#pragma unroll
        for (int i = 0; i < Tn; ++i) sum += expf(av[i] - mx);
        float e = (lane < Tn) ? E[s * Tn + lane] : 0.f;
        float nw = mx + logf(sum) + e;
        if (lane < Tn && s < len) alpha = nw;
    }
    float v = (lane < Tn) ? alpha + end_[lane] : -1e30f;
    float mx = v;
#pragma unroll
    for (int o = 16; o; o >>= 1) mx = fmaxf(mx, __shfl_xor_sync(0xffffffffu, mx, o));
    float se = expf(v - mx);
#pragma unroll
    for (int o = 16; o; o >>= 1) se += __shfl_xor_sync(0xffffffffu, se, o);
    float logz = mx + logf(se);
    if (lane == 0) {
        float score = partial + start[tgt[0]] + E[tgt[0]] + end_[tgt[len - 1]];
        g_llh[b] = score - logz;
    }
}

__global__ void finalize_kernel(const int* __restrict__ lens, float* __restrict__ out) {
    float sl = 0.f;
    float smk = 0.f;
    for (int b = 0; b < Bn; ++b) { sl += g_llh[b]; smk += (float)lens[b]; }
    out[0] = -sl / smk;
}

// ---------------- launch ----------------
extern "C" void kernel_launch(void* const* d_in, const int* in_sizes, int n_in,
                              void* d_out, int out_size) {
    const float* char_emb  = (const float*)d_in[0];
    const float* conv_w    = (const float*)d_in[1];
    const float* conv_b    = (const float*)d_in[2];
    const float* word_emb  = (const float*)d_in[3];
    const float* w_ih_l0   = (const float*)d_in[4];
    const float* w_hh_l0   = (const float*)d_in[5];
    const float* b_ih_l0   = (const float*)d_in[6];
    const float* b_hh_l0   = (const float*)d_in[7];
    const float* w_ih_l1   = (const float*)d_in[8];
    const float* w_hh_l1   = (const float*)d_in[9];
    const float* b_ih_l1   = (const float*)d_in[10];
    const float* b_hh_l1   = (const float*)d_in[11];
    const float* mlp_w1    = (const float*)d_in[12];
    const float* mlp_b1    = (const float*)d_in[13];
    const float* mlp_w2    = (const float*)d_in[14];
    const float* mlp_b2    = (const float*)d_in[15];
    const float* crf_start = (const float*)d_in[16];
    const float* crf_end   = (const float*)d_in[17];
    const float* crf_trans = (const float*)d_in[18];
    const int* char_words  = (const int*)d_in[19];
    const int* cwi         = (const int*)d_in[21];
    const int* tokens      = (const int*)d_in[22];
    const int* tokens_len  = (const int*)d_in[23];
    const int* target      = (const int*)d_in[24];
    float* out = (float*)d_out;

    void* pv;
    cudaGetSymbolAddress(&pv, g_texts); float* p_texts = (float*)pv;
    cudaGetSymbolAddress(&pv, g_xg);    float* p_xg    = (float*)pv;
    cudaGetSymbolAddress(&pv, g_h0);    float* p_h0    = (float*)pv;
    cudaGetSymbolAddress(&pv, g_h1);    float* p_h1    = (float*)pv;
    cudaGetSymbolAddress(&pv, g_mlp);   float* p_mlp   = (float*)pv;
    cudaGetSymbolAddress(&pv, g_emis);  float* p_emis  = (float*)pv;

    const int M = Bn * Sn;  // 16384

    char_cnn_kernel<<<NWn + 1, 480>>>(char_emb, conv_w, conv_b, char_words);
    build_texts_kernel<<<M, 352>>>(word_emb, tokens, cwi);
    gemm_kernel<<<dim3(G6 / 128, M / 128), 256>>>(p_texts, w_ih_l0, b_ih_l0, p_xg,
                                                  M, G6, INW0, 0, 1);
    gru_kernel<<<2 * Bn, GT>>>(p_xg, w_hh_l0, b_hh_l0, tokens_len, p_h0);
    gemm_kernel<<<dim3(G6 / 128, M / 128), 256>>>(p_h0, w_ih_l1, b_ih_l1, p_xg,
                                                  M, G6, 256, 0, 1);
    gru_kernel<<<2 * Bn, GT>>>(p_xg, w_hh_l1, b_hh_l1, tokens_len, p_h1);
    gemm_kernel<<<dim3(1, M / 128), 256>>>(p_h1, mlp_w1, mlp_b1, p_mlp,
                                           M, Hn, 256, 1, 0);
    gemm_kernel<<<dim3(1, M / 128), 256>>>(p_mlp, mlp_w2, mlp_b2, p_emis,
                                           M, Tn, Hn, 0, 0);
    crf_kernel<<<Bn, 32>>>(crf_start, crf_end, crf_trans, target, tokens_len);
    finalize_kernel<<<1, 1>>>(tokens_len, out);
}